// round 17
// baseline (speedup 1.0000x reference)
#include <cuda_runtime.h>
#include <cuda_fp16.h>
#include <cstdint>

// MetapathGATConv fused kernel, R11: NB=8 nodes/CTA, 512 threads, 1 CTA/SM.
// Halves per-node W traffic (the dominant L1 term). Barrier-free fp16
// m16n8k16 GEMMs, LDG.256 W loads, ldmatrix A frags, half2 logits.

#define RREL   8
#define EMBED  256
#define NB     8
#define ROWS   64            // NB * RREL
#define HPW    132           // fp16 buffer pitch in 32-bit words (== 4 mod 32)
#define FPW    260           // fp32 xl pitch in floats
#define NTHREADS 512
#define KSTEPS 16            // 256 / 16
#define WMAT_U4 (KSTEPS * 8 * 64)   // 8192 uint4 per matrix

__device__ uint4 g_Wh[4 * WMAT_U4];   // Wl0|Wr0|Wl1|Wr1, fp16 pair-contiguous frags

__device__ __forceinline__ uint32_t h2(float lo, float hi) {
    uint32_t r;
    asm("cvt.rn.f16x2.f32 %0, %1, %2;" : "=r"(r) : "f"(hi), "f"(lo));
    return r;
}
__device__ __forceinline__ __half2 u2h(uint32_t w) {
    return *reinterpret_cast<__half2*>(&w);
}
__device__ __forceinline__ float leaky(float v) { return v > 0.f ? v : 0.2f * v; }

__device__ __forceinline__ void ldg256(uint32_t* r, const void* p) {
    asm volatile("ld.global.nc.v8.b32 {%0,%1,%2,%3,%4,%5,%6,%7}, [%8];"
        : "=r"(r[0]), "=r"(r[1]), "=r"(r[2]), "=r"(r[3]),
          "=r"(r[4]), "=r"(r[5]), "=r"(r[6]), "=r"(r[7])
        : "l"(p));
}
__device__ __forceinline__ void mma_f16(float* c, const uint32_t* a,
                                        uint32_t b0, uint32_t b1) {
    asm volatile(
        "mma.sync.aligned.m16n8k16.row.col.f32.f16.f16.f32 "
        "{%0,%1,%2,%3}, {%4,%5,%6,%7}, {%8,%9}, {%0,%1,%2,%3};"
        : "+f"(c[0]), "+f"(c[1]), "+f"(c[2]), "+f"(c[3])
        : "r"(a[0]), "r"(a[1]), "r"(a[2]), "r"(a[3]), "r"(b0), "r"(b1));
}
__device__ __forceinline__ void ldsm_x4(uint32_t* a, uint32_t smaddr) {
    asm volatile("ldmatrix.sync.aligned.m8n8.x4.shared.b16 {%0,%1,%2,%3}, [%4];"
                 : "=r"(a[0]), "=r"(a[1]), "=r"(a[2]), "=r"(a[3]) : "r"(smaddr));
}

// W repack, pair-contiguous (unchanged from R10).
__global__ void repack_W(const float* __restrict__ Wl0, const float* __restrict__ Wr0,
                         const float* __restrict__ Wl1, const float* __restrict__ Wr1)
{
    int idx = blockIdx.x * blockDim.x + threadIdx.x;   // 0..32767
    int q    = idx & 1;
    int lane = (idx >> 1) & 31;
    int nb   = (idx >> 6) & 7;
    int s    = (idx >> 9) & 15;
    int m    = idx >> 13;
    int g = lane >> 2, t = lane & 3;
    const float* W = (m == 0) ? Wl0 : (m == 1) ? Wr0 : (m == 2) ? Wl1 : Wr1;

    uint32_t r[4];
#pragma unroll
    for (int e = 0; e < 2; e++) {
        int nt = q * 2 + e;
        int n  = nb * 32 + nt * 8 + g;
        int k0 = s * 16 + 2 * t;
        r[2 * e + 0] = h2(W[k0 * EMBED + n],       W[(k0 + 1) * EMBED + n]);
        r[2 * e + 1] = h2(W[(k0 + 8) * EMBED + n], W[(k0 + 9) * EMBED + n]);
    }
    g_Wh[idx] = make_uint4(r[0], r[1], r[2], r[3]);
}

// Fused dual GEMM over A[64,256] fp16, barrier-free. 16 warps = 2 mb x 8 nb.
// DL -> fp16 (DLh) + fp32 (DLf). DR fp16. SMALL: rows node*8+7 (mb==0 warps
// only; qr = node 0..7), Wr loads skipped on mb==1.
template <bool SMALL>
__device__ __forceinline__ void gemm_dual(
    const uint4* __restrict__ WlF, const float* __restrict__ biasL,
    const uint4* __restrict__ WrF, const float* __restrict__ biasR,
    const uint32_t* __restrict__ Ah, uint32_t* __restrict__ DLh,
    float* __restrict__ DLf, uint32_t* __restrict__ DRh, int tid)
{
    const int wid = tid >> 5, lane = tid & 31;
    const int nb = wid & 7, mb = wid >> 3;
    const int qr = lane >> 2, qk = lane & 3;
    const int lrow = ((lane >> 3) & 1) * 8 + (lane & 7);
    const int lcol = (lane >> 4) * 4;
    const uint32_t abase = (uint32_t)__cvta_generic_to_shared(Ah);
    const bool doR = !SMALL || mb == 0;

    float accL[8][4];
    float accR[8][4];
#pragma unroll
    for (int t = 0; t < 8; t++)
#pragma unroll
        for (int j = 0; j < 4; j++) { accL[t][j] = 0.f; accR[t][j] = 0.f; }

    uint32_t wlA[8], wrA[8], wlB[8], wrB[8];
    ldg256(wlA, WlF + (0 * 8 + nb) * 64 + lane * 2);
    if (doR) ldg256(wrA, WrF + (0 * 8 + nb) * 64 + lane * 2);

    auto body = [&](int s, const uint32_t* wl, const uint32_t* wr) {
        uint32_t a[2][4];
#pragma unroll
        for (int mt = 0; mt < 2; mt++)
            ldsm_x4(a[mt], abase +
                    4u * ((mb * 32 + mt * 16 + lrow) * HPW + s * 8 + lcol));

        uint32_t as[4];
        if (SMALL && mb == 0) {
            int base = (qr * 8 + 7) * HPW + s * 8;
            as[0] = Ah[base + qk];
            as[2] = Ah[base + qk + 4];
            as[1] = as[0]; as[3] = as[2];
        }
#pragma unroll
        for (int mt = 0; mt < 2; mt++) {
            mma_f16(accL[mt * 4 + 0], a[mt], wl[0], wl[1]);
            mma_f16(accL[mt * 4 + 1], a[mt], wl[2], wl[3]);
            mma_f16(accL[mt * 4 + 2], a[mt], wl[4], wl[5]);
            mma_f16(accL[mt * 4 + 3], a[mt], wl[6], wl[7]);
        }
        if (!SMALL) {
#pragma unroll
            for (int mt = 0; mt < 2; mt++) {
                mma_f16(accR[mt * 4 + 0], a[mt], wr[0], wr[1]);
                mma_f16(accR[mt * 4 + 1], a[mt], wr[2], wr[3]);
                mma_f16(accR[mt * 4 + 2], a[mt], wr[4], wr[5]);
                mma_f16(accR[mt * 4 + 3], a[mt], wr[6], wr[7]);
            }
        } else if (mb == 0) {
            mma_f16(accR[0], as, wr[0], wr[1]);
            mma_f16(accR[1], as, wr[2], wr[3]);
            mma_f16(accR[2], as, wr[4], wr[5]);
            mma_f16(accR[3], as, wr[6], wr[7]);
        }
    };

#pragma unroll
    for (int s = 0; s < KSTEPS; s += 2) {
        ldg256(wlB, WlF + ((s + 1) * 8 + nb) * 64 + lane * 2);
        if (doR) ldg256(wrB, WrF + ((s + 1) * 8 + nb) * 64 + lane * 2);
        body(s, wlA, wrA);
        if (s + 2 < KSTEPS) {
            ldg256(wlA, WlF + ((s + 2) * 8 + nb) * 64 + lane * 2);
            if (doR) ldg256(wrA, WrF + ((s + 2) * 8 + nb) * 64 + lane * 2);
        }
        body(s + 1, wlB, wrB);
    }

    // epilogue: DL dual store (fp16 + fp32); DR fp16.
#pragma unroll
    for (int mt = 0; mt < 2; mt++)
#pragma unroll
        for (int nt = 0; nt < 4; nt++) {
            int row = mb * 32 + mt * 16 + qr;
            int c0  = nb * 32 + nt * 8 + 2 * qk;
            int wc  = c0 >> 1;
            float bx = biasL[c0], by = biasL[c0 + 1];
            float v0 = accL[mt * 4 + nt][0] + bx;
            float v1 = accL[mt * 4 + nt][1] + by;
            float v2 = accL[mt * 4 + nt][2] + bx;
            float v3 = accL[mt * 4 + nt][3] + by;
            DLh[row * HPW + wc]       = h2(v0, v1);
            DLh[(row + 8) * HPW + wc] = h2(v2, v3);
            *reinterpret_cast<float2*>(DLf + row * FPW + c0) = make_float2(v0, v1);
            *reinterpret_cast<float2*>(DLf + (row + 8) * FPW + c0) =
                make_float2(v2, v3);
        }
    if (!SMALL) {
#pragma unroll
        for (int mt = 0; mt < 2; mt++)
#pragma unroll
            for (int nt = 0; nt < 4; nt++) {
                int row = mb * 32 + mt * 16 + qr;
                int c0  = nb * 32 + nt * 8 + 2 * qk;
                int wc  = c0 >> 1;
                float bx = biasR[c0], by = biasR[c0 + 1];
                DRh[row * HPW + wc] =
                    h2(accR[mt * 4 + nt][0] + bx, accR[mt * 4 + nt][1] + by);
                DRh[(row + 8) * HPW + wc] =
                    h2(accR[mt * 4 + nt][2] + bx, accR[mt * 4 + nt][3] + by);
            }
    } else if (mb == 0) {
#pragma unroll
        for (int nt = 0; nt < 4; nt++) {
            int c0 = nb * 32 + nt * 8 + 2 * qk;
            int wc = c0 >> 1;
            DRh[(qr * 8 + 7) * HPW + wc] =
                h2(accR[nt][0] + biasR[c0], accR[nt][1] + biasR[c0 + 1]);
        }
    }
}

extern "C" __global__ void __launch_bounds__(NTHREADS, 1)
metapath_gat_kernel(
    const float* __restrict__ x,
    const float* __restrict__ bl0, const float* __restrict__ br0,
    const float* __restrict__ att0, const float* __restrict__ bias0,
    const float* __restrict__ bl1, const float* __restrict__ br1,
    const float* __restrict__ att1, const float* __restrict__ bias1,
    float* __restrict__ outEmb, float* __restrict__ outBeta)
{
    extern __shared__ uint32_t smemw[];
    uint32_t* bufHw  = smemw;                     // [64][132] fp16 words
    uint32_t* bufXRw = bufHw  + ROWS * HPW;       // [64][132] fp16 (xr)
    uint32_t* bufXLh = bufXRw + ROWS * HPW;       // [64][132] fp16 xl (logits copy)
    float*    bufXLf = (float*)(bufXLh + ROWS * HPW);  // [64][260] fp32 xl
    float*    alphaS = bufXLf + ROWS * FPW;       // [nd][i][h][j] fp32 = 2048
    float*    betaS  = alphaS + 2048;             // 256
    uint32_t* attH0  = (uint32_t*)(betaS + 256);  // [4][32] half2 words
    uint32_t* attH1  = attH0 + 128;

    const int tid = threadIdx.x;
    const int g = blockIdx.x;
    const float* xg = x + (size_t)g * (NB * RREL * EMBED);

    if (tid < 128) {
        attH0[tid] = h2(att0[2 * tid], att0[2 * tid + 1]);
        attH1[tid] = h2(att1[2 * tid], att1[2 * tid + 1]);
    }

    // Phase 1: x -> relu -> fp16 -> bufH (LDG.256 + STS.128)
#pragma unroll
    for (int i = 0; i < 4; i++) {
        int idx = tid + i * NTHREADS;             // 0..2047 float8
        uint32_t rr[8];
        ldg256(rr, xg + idx * 8);
        int f = idx * 8;
        int r = f >> 8;
        int d = f & 255;
        const float* fv = reinterpret_cast<const float*>(rr);
        uint4 p;
        p.x = h2(fmaxf(fv[0], 0.f), fmaxf(fv[1], 0.f));
        p.y = h2(fmaxf(fv[2], 0.f), fmaxf(fv[3], 0.f));
        p.z = h2(fmaxf(fv[4], 0.f), fmaxf(fv[5], 0.f));
        p.w = h2(fmaxf(fv[6], 0.f), fmaxf(fv[7], 0.f));
        *reinterpret_cast<uint4*>(bufHw + r * HPW + (d >> 1)) = p;
    }
    __syncthreads();

    // Phase 2: fused layer-0 GEMMs
    gemm_dual<false>(g_Wh + 0 * WMAT_U4, bl0, g_Wh + 1 * WMAT_U4, br0,
                     bufHw, bufXLh, bufXLf, bufXRw, tid);
    __syncthreads();

    // Phase 3: logits0 + softmax over j, half2 math, LDS.64.
    // 16 warps = (nd 0..7, ihalf 0..1); lane = (j, h).
    {
        int w = tid >> 5, lane = tid & 31;
        int nd = w & 7, ihalf = w >> 3;
        int j = lane >> 2, h = lane & 3;
        const uint2* at2 = reinterpret_cast<const uint2*>(attH0) + h * 16;
        const uint2* xl2 = reinterpret_cast<const uint2*>(bufXLh)
                           + (nd * 8 + j) * (HPW / 2) + h * 16;
        const uint2* xr2 = reinterpret_cast<const uint2*>(bufXRw)
                           + (nd * 8 + ihalf * 4) * (HPW / 2) + h * 16;
        const __half2 zz  = __float2half2_rn(0.f);
        const __half2 c02 = __float2half2_rn(0.2f);
        float sa[4];
#pragma unroll
        for (int ii = 0; ii < 4; ii++) sa[ii] = 0.f;
#pragma unroll 4
        for (int p = 0; p < 16; p++) {
            int cc = (p + h) & 15;                // pair-granular rotation
            uint2 xlp = xl2[cc], atp = at2[cc];
            __half2 xla = u2h(xlp.x), xlb = u2h(xlp.y);
            __half2 ata = u2h(atp.x), atb = u2h(atp.y);
#pragma unroll
            for (int ii = 0; ii < 4; ii++) {
                uint2 xrp = xr2[ii * (HPW / 2) + cc];
                __half2 v0 = __hadd2(u2h(xrp.x), xla);
                __half2 v1 = __hadd2(u2h(xrp.y), xlb);
                __half2 l0 = __hfma2(__hmin2(v0, zz), c02, __hmax2(v0, zz));
                __half2 l1 = __hfma2(__hmin2(v1, zz), c02, __hmax2(v1, zz));
                float2 p0 = __half22float2(__hmul2(ata, l0));
                float2 p1 = __half22float2(__hmul2(atb, l1));
                sa[ii] += (p0.x + p0.y) + (p1.x + p1.y);
            }
        }
#pragma unroll
        for (int ii = 0; ii < 4; ii++) {
            float s = sa[ii];
            float m = s;
            m = fmaxf(m, __shfl_xor_sync(0xffffffffu, m, 4));
            m = fmaxf(m, __shfl_xor_sync(0xffffffffu, m, 8));
            m = fmaxf(m, __shfl_xor_sync(0xffffffffu, m, 16));
            float e = __expf(s - m);
            float sum = e;
            sum += __shfl_xor_sync(0xffffffffu, sum, 4);
            sum += __shfl_xor_sync(0xffffffffu, sum, 8);
            sum += __shfl_xor_sync(0xffffffffu, sum, 16);
            alphaS[((nd * 8 + ihalf * 4 + ii) * 4 + h) * 8 + j] = e / sum;
        }
    }
    __syncthreads();

    // Phase 4: h1 = relu(alpha @ xl0 + bias0) -> bufH fp16 (fp32 inputs).
    // 512 thr: col pair c0 = 2*(tid&127); node pair = (tid>>7)*2 + {0,1}.
    {
        int c0 = 2 * (tid & 127);
        int ndb = (tid >> 7) * 2;
        int h = c0 >> 6;
        float b0a = bias0[c0], b0b = bias0[c0 + 1];
#pragma unroll
        for (int nn = 0; nn < 2; nn++) {
            int nd = ndb + nn;
            float xa[8], xb[8];
#pragma unroll
            for (int j = 0; j < 8; j++) {
                float2 v = *reinterpret_cast<const float2*>(
                    bufXLf + (nd * 8 + j) * FPW + c0);
                xa[j] = v.x; xb[j] = v.y;
            }
#pragma unroll
            for (int i = 0; i < 8; i++) {
                const float4* ap = reinterpret_cast<const float4*>(
                    alphaS + ((nd * 8 + i) * 4 + h) * 8);
                float4 a03 = ap[0];
                float4 a47 = ap[1];
                float al[8] = {a03.x, a03.y, a03.z, a03.w,
                               a47.x, a47.y, a47.z, a47.w};
                float sa = b0a, sb = b0b;
#pragma unroll
                for (int j = 0; j < 8; j++) {
                    sa += al[j] * xa[j];
                    sb += al[j] * xb[j];
                }
                bufHw[(nd * 8 + i) * HPW + (c0 >> 1)] =
                    h2(fmaxf(sa, 0.f), fmaxf(sb, 0.f));
            }
        }
    }
    __syncthreads();

    // Phase 5: fused layer-1 GEMMs (xl1 full; xr1 self rows)
    gemm_dual<true>(g_Wh + 2 * WMAT_U4, bl1, g_Wh + 3 * WMAT_U4, br1,
                    bufHw, bufXLh, bufXLf, bufXRw, tid);
    __syncthreads();

    // Phase 6: logits1 + softmax over r -> beta (xl fp32, xr/att fp16)
    if (tid < 256) {
        int node = tid >> 5, lane = tid & 31;
        int r = lane >> 2, h = lane & 3;
        const uint32_t* at2 = attH1 + h * 32;
        const uint32_t* xr2 = bufXRw + (node * 8 + 7) * HPW + h * 32;
        const float*    xl  = bufXLf + (node * 8 + r) * FPW + h * 64;
        float s = 0.f;
#pragma unroll 4
        for (int c2 = 0; c2 < 32; c2++) {
            int cc = (c2 + h) & 31;
            float2 xrv = __half22float2(u2h(xr2[cc]));
            float2 av  = __half22float2(u2h(at2[cc]));
            float2 xlv = *reinterpret_cast<const float2*>(xl + 2 * cc);
            s += av.x * leaky(xrv.x + xlv.x) + av.y * leaky(xrv.y + xlv.y);
        }
        float m = s;
        m = fmaxf(m, __shfl_xor_sync(0xffffffffu, m, 4));
        m = fmaxf(m, __shfl_xor_sync(0xffffffffu, m, 8));
        m = fmaxf(m, __shfl_xor_sync(0xffffffffu, m, 16));
        float e = __expf(s - m);
        float sum = e;
        sum += __shfl_xor_sync(0xffffffffu, sum, 4);
        sum += __shfl_xor_sync(0xffffffffu, sum, 8);
        sum += __shfl_xor_sync(0xffffffffu, sum, 16);
        float beta = e / sum;
        betaS[(node * 8 + r) * 4 + h] = beta;
        outBeta[(size_t)(g * NB + node) * 32 + r * 4 + h] = beta;
    }
    __syncthreads();

    // Phase 7: out = relu(beta @ xl1 + bias1), xl fp32.
    // col = tid & 255; node half = tid >> 8 (4 nodes each).
    {
        int col = tid & 255;
        int half = tid >> 8;
        int h = col >> 6;
        float b1 = bias1[col];
#pragma unroll
        for (int nn = 0; nn < 4; nn++) {
            int nd = half * 4 + nn;
            float s = b1;
#pragma unroll
            for (int r = 0; r < 8; r++)
                s += betaS[(nd * 8 + r) * 4 + h] * bufXLf[(nd * 8 + r) * FPW + col];
            outEmb[(size_t)(g * NB + nd) * 256 + col] = fmaxf(s, 0.f);
        }
    }
}

extern "C" void kernel_launch(void* const* d_in, const int* in_sizes, int n_in,
                              void* d_out, int out_size)
{
    const float* x     = (const float*)d_in[0];
    const float* Wl0   = (const float*)d_in[1];
    const float* bl0   = (const float*)d_in[2];
    const float* Wr0   = (const float*)d_in[3];
    const float* br0   = (const float*)d_in[4];
    const float* att0  = (const float*)d_in[5];
    const float* bias0 = (const float*)d_in[6];
    const float* Wl1   = (const float*)d_in[7];
    const float* bl1   = (const float*)d_in[8];
    const float* Wr1   = (const float*)d_in[9];
    const float* br1   = (const float*)d_in[10];
    const float* att1  = (const float*)d_in[11];
    const float* bias1 = (const float*)d_in[12];

    int nodes = in_sizes[0] / (RREL * EMBED);
    float* outEmb  = (float*)d_out;
    float* outBeta = outEmb + (size_t)nodes * EMBED;

    repack_W<<<128, 256>>>(Wl0, Wr0, Wl1, Wr1);

    size_t smem_words = 3 * ROWS * HPW + ROWS * FPW + 2048 + 256 + 256;
    size_t smem_bytes = smem_words * 4;
    cudaFuncSetAttribute(metapath_gat_kernel,
                         cudaFuncAttributeMaxDynamicSharedMemorySize,
                         (int)smem_bytes);

    metapath_gat_kernel<<<nodes / NB, NTHREADS, smem_bytes>>>(
        x, bl0, br0, att0, bias0, bl1, br1, att1, bias1, outEmb, outBeta);
}